// round 9
// baseline (speedup 1.0000x reference)
#include <cuda_runtime.h>
#include <cuda_fp16.h>

// ----------------------------------------------------------------------------
// ScaledDotProduct on GB300, round 8:
//   fp16 pipeline (fp32 accum), mma.sync m16n8k16,
//   CTA tile 256x128, 8 warps x (64x64), BK=32,
//   ldmatrix.x4 fragment loads (trans for [K,N] B), 3-stage cp.async.
// ----------------------------------------------------------------------------

#define BM 256
#define BN 128
#define BK 32
#define LDAh  40   // halves: 32 + 8 pad (80B rows: ldmatrix conflict-free)
#define LDB0h 40   // B mode0 stored [n][k]
#define LDB1h 136  // B mode1 stored [k][n] (272B rows: ldmatrix conflict-free)
#define NSTG 3

// scratch (__device__ globals)
__device__ __align__(256) __half g_qh[(size_t)4 * 4096 * 1024];
__device__ __align__(256) __half g_kh[(size_t)4 * 4096 * 1024];
__device__ __align__(256) __half g_vh[(size_t)4 * 4096 * 1024];
__device__ __align__(256) __half g_wq[(size_t)256 * 1024];
__device__ __align__(256) __half g_wk[(size_t)256 * 1024];
__device__ __align__(256) __half g_wv[(size_t)1024 * 1024];
__device__ __align__(256) __half g_qp[(size_t)4 * 4096 * 256];
__device__ __align__(256) __half g_kp[(size_t)4 * 4096 * 256];
__device__ __align__(256) __half g_vp[(size_t)4 * 4096 * 1024];
__device__ __align__(256) __half g_z [(size_t)4 * 4096 * 4096];

__device__ __forceinline__ void cpasync16(void* dst, const void* src) {
    unsigned int d = (unsigned int)__cvta_generic_to_shared(dst);
    asm volatile("cp.async.cg.shared.global [%0], [%1], 16;" :: "r"(d), "l"(src));
}

__device__ __forceinline__ void ldsm4(unsigned int* r, const void* p) {
    unsigned int a = (unsigned int)__cvta_generic_to_shared(p);
    asm volatile("ldmatrix.sync.aligned.m8n8.x4.shared.b16 {%0,%1,%2,%3}, [%4];"
                 : "=r"(r[0]), "=r"(r[1]), "=r"(r[2]), "=r"(r[3]) : "r"(a));
}
__device__ __forceinline__ void ldsm4t(unsigned int* r, const void* p) {
    unsigned int a = (unsigned int)__cvta_generic_to_shared(p);
    asm volatile("ldmatrix.sync.aligned.m8n8.x4.trans.shared.b16 {%0,%1,%2,%3}, [%4];"
                 : "=r"(r[0]), "=r"(r[1]), "=r"(r[2]), "=r"(r[3]) : "r"(a));
}

__device__ __forceinline__ void mma16(float* c, const unsigned int* a, const unsigned int* b) {
    asm volatile(
        "mma.sync.aligned.m16n8k16.row.col.f32.f16.f16.f32 "
        "{%0,%1,%2,%3}, {%4,%5,%6,%7}, {%8,%9}, {%0,%1,%2,%3};\n"
        : "+f"(c[0]), "+f"(c[1]), "+f"(c[2]), "+f"(c[3])
        : "r"(a[0]), "r"(a[1]), "r"(a[2]), "r"(a[3]),
          "r"(b[0]), "r"(b[1]));
}

// sigma(x) = 1/(1 + 2^(-x*log2 e)) without any MUFU op.
__device__ __forceinline__ float sigmoid_fast(float x) {
    float t = x * -1.4426950408889634f;
    t = fminf(fmaxf(t, -30.0f), 30.0f);
    float fi = rintf(t);
    float f  = t - fi;                       // [-0.5, 0.5]
    float p = 1.33335581e-3f;
    p = fmaf(p, f, 9.61812911e-3f);
    p = fmaf(p, f, 5.55041087e-2f);
    p = fmaf(p, f, 2.40226507e-1f);
    p = fmaf(p, f, 6.93147181e-1f);
    p = fmaf(p, f, 1.0f);
    int ei = (int)fi;
    float s = __int_as_float((ei + 127) << 23);   // 2^fi
    float d = fmaf(p, s, 1.0f);                   // 1 + 2^t
    float r = __int_as_float(0x7EF311C3 - __float_as_int(d));
    r = r * fmaf(-d, r, 2.0f);
    r = r * fmaf(-d, r, 2.0f);
    r = r * fmaf(-d, r, 2.0f);
    return r;
}

__global__ void to_half(const float* __restrict__ in, __half* __restrict__ out, int n4) {
    int i = blockIdx.x * blockDim.x + threadIdx.x;
    if (i < n4) {
        float4 v = reinterpret_cast<const float4*>(in)[i];
        __half2 h0 = __floats2half2_rn(v.x, v.y);
        __half2 h1 = __floats2half2_rn(v.z, v.w);
        reinterpret_cast<uint2*>(out)[i] =
            make_uint2(*reinterpret_cast<unsigned int*>(&h0),
                       *reinterpret_cast<unsigned int*>(&h1));
    }
}

// MODE_B: 0 -> B is [N,K] half (A @ B^T); 1 -> B is [K,N] half (A @ B)
// EPI:    0 -> fp32 store, 1 -> +bias half store, 2 -> sigmoid(x/16) half store
template <int MODE_B, int EPI>
__global__ __launch_bounds__(256)
void gemm_f16(const __half* __restrict__ A, const __half* __restrict__ B,
              const float* __restrict__ bias, void* __restrict__ Cv,
              int N, int K,
              size_t sA, size_t sB, size_t sC)
{
    extern __shared__ __half sm[];
    constexpr int ASZ = BM * LDAh;                                 // 10240 halves
    constexpr int BSZ = (MODE_B == 0) ? BN * LDB0h : BK * LDB1h;   // 5120 / 4352
    constexpr int STW = ASZ + BSZ;

    const __half* Ab = A + (size_t)blockIdx.z * sA;
    const __half* Bb = B + (size_t)blockIdx.z * sB;

    const int bMr  = blockIdx.x * BM;
    const int bNc  = blockIdx.y * BN;
    const int tid  = threadIdx.x;
    const int lane = tid & 31;
    const int warp = tid >> 5;
    const int wm   = (warp >> 1) * 64;   // 4 warps along M
    const int wn   = (warp & 1) * 64;    // 2 warps along N

    float acc[4][8][4];
#pragma unroll
    for (int i = 0; i < 4; i++)
#pragma unroll
        for (int j = 0; j < 8; j++)
#pragma unroll
            for (int t = 0; t < 4; t++) acc[i][j][t] = 0.0f;

    const int nch = K / BK;

    auto stage = [&](int s, int k0) {
        __half* Ad = sm + s * STW;
        __half* Bd = Ad + ASZ;
        // A tile: BM(256) x BK(32) halves ; 4 x 16B per row, 1024 chunks
#pragma unroll
        for (int it = 0; it < 4; it++) {
            int f4 = tid + it * 256;
            int r  = f4 >> 2;
            int cc = (f4 & 3) << 3;   // halves
            cpasync16(&Ad[r * LDAh + cc], Ab + (size_t)(bMr + r) * K + k0 + cc);
        }
        if (MODE_B == 0) {
            // B[n][k]: 128 x 32 halves, 512 chunks
#pragma unroll
            for (int it = 0; it < 2; it++) {
                int f4 = tid + it * 256;
                int r  = f4 >> 2;
                int cc = (f4 & 3) << 3;
                cpasync16(&Bd[r * LDB0h + cc], Bb + (size_t)(bNc + r) * K + k0 + cc);
            }
        } else {
            // B[k][n]: 32 x 128 halves, 512 chunks
#pragma unroll
            for (int it = 0; it < 2; it++) {
                int f4 = tid + it * 256;
                int r  = f4 >> 4;
                int cc = (f4 & 15) << 3;
                cpasync16(&Bd[r * LDB1h + cc], Bb + (size_t)(k0 + r) * N + bNc + cc);
            }
        }
        asm volatile("cp.async.commit_group;");
    };

    stage(0, 0);
    if (nch > 1) stage(1, BK);

    for (int c = 0; c < nch; c++) {
        if (c + 2 < nch) {
            stage((c + 2) % NSTG, (c + 2) * BK);
            asm volatile("cp.async.wait_group 2;");
        } else if (c + 1 < nch) {
            asm volatile("cp.async.wait_group 1;");
        } else {
            asm volatile("cp.async.wait_group 0;");
        }
        __syncthreads();

        const __half* Asb = sm + (c % NSTG) * STW;
        const __half* Bsb = Asb + ASZ;

#pragma unroll
        for (int ks = 0; ks < 2; ks++) {            // two k16 steps per BK=32
            const int kb = ks * 16;                 // halves
            unsigned int a[4][4], bf[8][2];
            // A fragments: 4 x 16x16 tiles via ldmatrix.x4
#pragma unroll
            for (int i = 0; i < 4; i++) {
                const int row = wm + i * 16 + (lane & 15);
                const int col = kb + ((lane >> 4) << 3);
                ldsm4(a[i], &Asb[row * LDAh + col]);
            }
            // B fragments: 4 x ldmatrix.x4, each covers two n8 tiles x k16
#pragma unroll
            for (int jj = 0; jj < 4; jj++) {
                unsigned int r[4];
                if (MODE_B == 0) {
                    const int row = wn + jj * 16 + (lane & 7) + ((lane >> 4) << 3);
                    const int col = kb + (lane & 8);
                    ldsm4(r, &Bsb[row * LDB0h + col]);
                } else {
                    const int row = kb + (lane & 15);
                    const int col = wn + jj * 16 + ((lane >> 4) << 3);
                    ldsm4t(r, &Bsb[row * LDB1h + col]);
                }
                bf[2 * jj + 0][0] = r[0];
                bf[2 * jj + 0][1] = r[1];
                bf[2 * jj + 1][0] = r[2];
                bf[2 * jj + 1][1] = r[3];
            }
#pragma unroll
            for (int i = 0; i < 4; i++)
#pragma unroll
                for (int j = 0; j < 8; j++)
                    mma16(acc[i][j], a[i], bf[j]);
        }
        __syncthreads();
    }

    // ---- epilogue ----
#pragma unroll
    for (int i = 0; i < 4; i++) {
        const int row0 = bMr + wm + i * 16 + (lane >> 2);
#pragma unroll
        for (int j = 0; j < 8; j++) {
            const int col0 = bNc + wn + j * 8 + ((lane & 3) << 1);
            float v0 = acc[i][j][0], v1 = acc[i][j][1];
            float v2 = acc[i][j][2], v3 = acc[i][j][3];
            if (EPI == 0) {
                float* Cb = (float*)Cv + (size_t)blockIdx.z * sC;
                *reinterpret_cast<float2*>(Cb + (size_t)row0 * N + col0) =
                    make_float2(v0, v1);
                *reinterpret_cast<float2*>(Cb + (size_t)(row0 + 8) * N + col0) =
                    make_float2(v2, v3);
            } else {
                if (EPI == 1) {
                    float b0 = bias[col0], b1 = bias[col0 + 1];
                    v0 += b0; v1 += b1; v2 += b0; v3 += b1;
                }
                if (EPI == 2) {
                    v0 = sigmoid_fast(0.0625f * v0);
                    v1 = sigmoid_fast(0.0625f * v1);
                    v2 = sigmoid_fast(0.0625f * v2);
                    v3 = sigmoid_fast(0.0625f * v3);
                }
                __half* Cb = (__half*)Cv + (size_t)blockIdx.z * sC;
                *reinterpret_cast<__half2*>(Cb + (size_t)row0 * N + col0) =
                    __floats2half2_rn(v0, v1);
                *reinterpret_cast<__half2*>(Cb + (size_t)(row0 + 8) * N + col0) =
                    __floats2half2_rn(v2, v3);
            }
        }
    }
}

extern "C" void kernel_launch(void* const* d_in, const int* in_sizes, int n_in,
                              void* d_out, int out_size)
{
    (void)in_sizes; (void)n_in; (void)out_size;
    const float* q  = (const float*)d_in[0];
    const float* k  = (const float*)d_in[1];
    const float* v  = (const float*)d_in[2];
    const float* Wq = (const float*)d_in[3];
    const float* bq = (const float*)d_in[4];
    const float* Wk = (const float*)d_in[5];
    const float* bk = (const float*)d_in[6];
    const float* Wv = (const float*)d_in[7];
    const float* bv = (const float*)d_in[8];
    float* out = (float*)d_out;

    __half *qh, *kh, *vh, *wq, *wk, *wv, *qp, *kp, *vp, *z;
    cudaGetSymbolAddress((void**)&qh, g_qh);
    cudaGetSymbolAddress((void**)&kh, g_kh);
    cudaGetSymbolAddress((void**)&vh, g_vh);
    cudaGetSymbolAddress((void**)&wq, g_wq);
    cudaGetSymbolAddress((void**)&wk, g_wk);
    cudaGetSymbolAddress((void**)&wv, g_wv);
    cudaGetSymbolAddress((void**)&qp, g_qp);
    cudaGetSymbolAddress((void**)&kp, g_kp);
    cudaGetSymbolAddress((void**)&vp, g_vp);
    cudaGetSymbolAddress((void**)&z,  g_z);

    const size_t SM0 = NSTG * (size_t)(BM * LDAh + BN * LDB0h) * 2;  // 92160 B
    const size_t SM1 = NSTG * (size_t)(BM * LDAh + BK * LDB1h) * 2;  // 87552 B
    cudaFuncSetAttribute(gemm_f16<0, 1>, cudaFuncAttributeMaxDynamicSharedMemorySize, (int)SM0);
    cudaFuncSetAttribute(gemm_f16<0, 2>, cudaFuncAttributeMaxDynamicSharedMemorySize, (int)SM0);
    cudaFuncSetAttribute(gemm_f16<1, 0>, cudaFuncAttributeMaxDynamicSharedMemorySize, (int)SM1);

    // prepass: fp32 -> fp16
    const int n4_qkv = (4 * 4096 * 1024) / 4;
    const int n4_wqk = (256 * 1024) / 4;
    const int n4_wv  = (1024 * 1024) / 4;
    to_half<<<(n4_qkv + 255) / 256, 256>>>(q,  qh, n4_qkv);
    to_half<<<(n4_qkv + 255) / 256, 256>>>(k,  kh, n4_qkv);
    to_half<<<(n4_qkv + 255) / 256, 256>>>(v,  vh, n4_qkv);
    to_half<<<(n4_wqk + 255) / 256, 256>>>(Wq, wq, n4_wqk);
    to_half<<<(n4_wqk + 255) / 256, 256>>>(Wk, wk, n4_wqk);
    to_half<<<(n4_wv  + 255) / 256, 256>>>(Wv, wv, n4_wv);

    // Projections: M = 16384, K = 1024, W is [N,K].
    gemm_f16<0, 1><<<dim3(64, 2, 1), 256, SM0>>>(qh, wq, bq, qp,  256, 1024, 0, 0, 0);
    gemm_f16<0, 1><<<dim3(64, 2, 1), 256, SM0>>>(kh, wk, bk, kp,  256, 1024, 0, 0, 0);
    gemm_f16<0, 1><<<dim3(64, 8, 1), 256, SM0>>>(vh, wv, bv, vp, 1024, 1024, 0, 0, 0);

    // Scores + sigmoid: per batch M = N = 4096, K = 256.
    gemm_f16<0, 2><<<dim3(16, 32, 4), 256, SM0>>>(
        qp, kp, nullptr, z, 4096, 256,
        (size_t)4096 * 256, (size_t)4096 * 256, (size_t)4096 * 4096);

    // Output: per batch M = 4096, N = 1024, K = 4096; vp is [K,N].
    gemm_f16<1, 0><<<dim3(16, 8, 4), 256, SM1>>>(
        z, vp, nullptr, out, 1024, 4096,
        (size_t)4096 * 4096, (size_t)4096 * 1024, (size_t)4096 * 1024);
}

// round 11
// speedup vs baseline: 1.2260x; 1.2260x over previous
#include <cuda_runtime.h>
#include <cuda_fp16.h>

// ----------------------------------------------------------------------------
// ScaledDotProduct on GB300, round 9:
//   fp16 pipeline (fp32 accum), mma.sync m16n8k16,
//   CTA tile 128x128, 8 warps x (64x32), 2 CTA/SM,
//   ldmatrix.x4 fragment loads (validated in R9), 3-stage cp.async,
//   single fused prepass kernel (also fixes ncu launch targeting).
// ----------------------------------------------------------------------------

#define BM 128
#define BN 128
#define BK 32
#define LDAh  40   // halves: 32 + 8 pad (80B rows; ldmatrix conflict-free)
#define LDB0h 40   // B mode0 stored [n][k]
#define LDB1h 136  // B mode1 stored [k][n] (272B rows; ldmatrix conflict-free)
#define NSTG 3

// scratch (__device__ globals)
__device__ __align__(256) __half g_qh[(size_t)4 * 4096 * 1024];
__device__ __align__(256) __half g_kh[(size_t)4 * 4096 * 1024];
__device__ __align__(256) __half g_vh[(size_t)4 * 4096 * 1024];
__device__ __align__(256) __half g_wq[(size_t)256 * 1024];
__device__ __align__(256) __half g_wk[(size_t)256 * 1024];
__device__ __align__(256) __half g_wv[(size_t)1024 * 1024];
__device__ __align__(256) __half g_qp[(size_t)4 * 4096 * 256];
__device__ __align__(256) __half g_kp[(size_t)4 * 4096 * 256];
__device__ __align__(256) __half g_vp[(size_t)4 * 4096 * 1024];
__device__ __align__(256) __half g_z [(size_t)4 * 4096 * 4096];

__device__ __forceinline__ void cpasync16(void* dst, const void* src) {
    unsigned int d = (unsigned int)__cvta_generic_to_shared(dst);
    asm volatile("cp.async.cg.shared.global [%0], [%1], 16;" :: "r"(d), "l"(src));
}

__device__ __forceinline__ void ldsm4(unsigned int* r, const void* p) {
    unsigned int a = (unsigned int)__cvta_generic_to_shared(p);
    asm volatile("ldmatrix.sync.aligned.m8n8.x4.shared.b16 {%0,%1,%2,%3}, [%4];"
                 : "=r"(r[0]), "=r"(r[1]), "=r"(r[2]), "=r"(r[3]) : "r"(a));
}
__device__ __forceinline__ void ldsm4t(unsigned int* r, const void* p) {
    unsigned int a = (unsigned int)__cvta_generic_to_shared(p);
    asm volatile("ldmatrix.sync.aligned.m8n8.x4.trans.shared.b16 {%0,%1,%2,%3}, [%4];"
                 : "=r"(r[0]), "=r"(r[1]), "=r"(r[2]), "=r"(r[3]) : "r"(a));
}

__device__ __forceinline__ void mma16(float* c, const unsigned int* a, const unsigned int* b) {
    asm volatile(
        "mma.sync.aligned.m16n8k16.row.col.f32.f16.f16.f32 "
        "{%0,%1,%2,%3}, {%4,%5,%6,%7}, {%8,%9}, {%0,%1,%2,%3};\n"
        : "+f"(c[0]), "+f"(c[1]), "+f"(c[2]), "+f"(c[3])
        : "r"(a[0]), "r"(a[1]), "r"(a[2]), "r"(a[3]),
          "r"(b[0]), "r"(b[1]));
}

// sigma(x) = 1/(1 + 2^(-x*log2 e)) without any MUFU op.
__device__ __forceinline__ float sigmoid_fast(float x) {
    float t = x * -1.4426950408889634f;
    t = fminf(fmaxf(t, -30.0f), 30.0f);
    float fi = rintf(t);
    float f  = t - fi;                       // [-0.5, 0.5]
    float p = 1.33335581e-3f;
    p = fmaf(p, f, 9.61812911e-3f);
    p = fmaf(p, f, 5.55041087e-2f);
    p = fmaf(p, f, 2.40226507e-1f);
    p = fmaf(p, f, 6.93147181e-1f);
    p = fmaf(p, f, 1.0f);
    int ei = (int)fi;
    float s = __int_as_float((ei + 127) << 23);   // 2^fi
    float d = fmaf(p, s, 1.0f);                   // 1 + 2^t
    float r = __int_as_float(0x7EF311C3 - __float_as_int(d));
    r = r * fmaf(-d, r, 2.0f);
    r = r * fmaf(-d, r, 2.0f);
    r = r * fmaf(-d, r, 2.0f);
    return r;
}

// One launch converts all six tensors (segment selected by blockIdx.y).
__global__ void to_half_all(const float* __restrict__ q,  const float* __restrict__ k,
                            const float* __restrict__ v,  const float* __restrict__ Wq,
                            const float* __restrict__ Wk, const float* __restrict__ Wv,
                            __half* __restrict__ qh, __half* __restrict__ kh,
                            __half* __restrict__ vh, __half* __restrict__ wq,
                            __half* __restrict__ wk, __half* __restrict__ wv)
{
    const int seg = blockIdx.y;
    const float* in; __half* out; int n4;
    const int n4_qkv = (4 * 4096 * 1024) / 4;
    const int n4_wqk = (256 * 1024) / 4;
    const int n4_wv  = (1024 * 1024) / 4;
    switch (seg) {
        case 0: in = q;  out = qh; n4 = n4_qkv; break;
        case 1: in = k;  out = kh; n4 = n4_qkv; break;
        case 2: in = v;  out = vh; n4 = n4_qkv; break;
        case 3: in = Wq; out = wq; n4 = n4_wqk; break;
        case 4: in = Wk; out = wk; n4 = n4_wqk; break;
        default:in = Wv; out = wv; n4 = n4_wv;  break;
    }
    int i = blockIdx.x * blockDim.x + threadIdx.x;
    if (i < n4) {
        float4 val = reinterpret_cast<const float4*>(in)[i];
        __half2 h0 = __floats2half2_rn(val.x, val.y);
        __half2 h1 = __floats2half2_rn(val.z, val.w);
        reinterpret_cast<uint2*>(out)[i] =
            make_uint2(*reinterpret_cast<unsigned int*>(&h0),
                       *reinterpret_cast<unsigned int*>(&h1));
    }
}

// MODE_B: 0 -> B is [N,K] half (A @ B^T); 1 -> B is [K,N] half (A @ B)
// EPI:    0 -> fp32 store, 1 -> +bias half store, 2 -> sigmoid(x/16) half store
template <int MODE_B, int EPI>
__global__ __launch_bounds__(256, 2)
void gemm_f16(const __half* __restrict__ A, const __half* __restrict__ B,
              const float* __restrict__ bias, void* __restrict__ Cv,
              int N, int K,
              size_t sA, size_t sB, size_t sC)
{
    extern __shared__ __half sm[];
    constexpr int ASZ = BM * LDAh;                                 // 5120 halves
    constexpr int BSZ = (MODE_B == 0) ? BN * LDB0h : BK * LDB1h;   // 5120 / 4352
    constexpr int STW = ASZ + BSZ;

    const __half* Ab = A + (size_t)blockIdx.z * sA;
    const __half* Bb = B + (size_t)blockIdx.z * sB;

    const int bMr  = blockIdx.x * BM;
    const int bNc  = blockIdx.y * BN;
    const int tid  = threadIdx.x;
    const int lane = tid & 31;
    const int warp = tid >> 5;
    const int wm   = (warp >> 2) * 64;   // 2 warps along M
    const int wn   = (warp & 3) * 32;    // 4 warps along N

    float acc[4][4][4];
#pragma unroll
    for (int i = 0; i < 4; i++)
#pragma unroll
        for (int j = 0; j < 4; j++)
#pragma unroll
            for (int t = 0; t < 4; t++) acc[i][j][t] = 0.0f;

    const int nch = K / BK;

    auto stage = [&](int s, int k0) {
        __half* Ad = sm + s * STW;
        __half* Bd = Ad + ASZ;
        // A tile: 128 x 32 halves = 512 x 16B chunks
#pragma unroll
        for (int it = 0; it < 2; it++) {
            int f4 = tid + it * 256;
            int r  = f4 >> 2;
            int cc = (f4 & 3) << 3;
            cpasync16(&Ad[r * LDAh + cc], Ab + (size_t)(bMr + r) * K + k0 + cc);
        }
        if (MODE_B == 0) {
#pragma unroll
            for (int it = 0; it < 2; it++) {
                int f4 = tid + it * 256;
                int r  = f4 >> 2;
                int cc = (f4 & 3) << 3;
                cpasync16(&Bd[r * LDB0h + cc], Bb + (size_t)(bNc + r) * K + k0 + cc);
            }
        } else {
#pragma unroll
            for (int it = 0; it < 2; it++) {
                int f4 = tid + it * 256;
                int r  = f4 >> 4;
                int cc = (f4 & 15) << 3;
                cpasync16(&Bd[r * LDB1h + cc], Bb + (size_t)(k0 + r) * N + bNc + cc);
            }
        }
        asm volatile("cp.async.commit_group;");
    };

    stage(0, 0);
    if (nch > 1) stage(1, BK);

    for (int c = 0; c < nch; c++) {
        if (c + 2 < nch) {
            stage((c + 2) % NSTG, (c + 2) * BK);
            asm volatile("cp.async.wait_group 2;");
        } else if (c + 1 < nch) {
            asm volatile("cp.async.wait_group 1;");
        } else {
            asm volatile("cp.async.wait_group 0;");
        }
        __syncthreads();

        const __half* Asb = sm + (c % NSTG) * STW;
        const __half* Bsb = Asb + ASZ;

#pragma unroll
        for (int ks = 0; ks < 2; ks++) {            // two k16 steps per BK=32
            const int kb = ks * 16;                 // halves
            unsigned int a[4][4], bf[4][2];
            // A fragments: 4 x (16x16) tiles via ldmatrix.x4 (validated in R9)
#pragma unroll
            for (int i = 0; i < 4; i++) {
                const int row = wm + i * 16 + (lane & 15);
                const int col = kb + ((lane >> 4) << 3);
                ldsm4(a[i], &Asb[row * LDAh + col]);
            }
            // B fragments: 2 x ldmatrix.x4, each covers two n8 tiles x k16
#pragma unroll
            for (int jj = 0; jj < 2; jj++) {
                unsigned int r[4];
                if (MODE_B == 0) {
                    const int row = wn + jj * 16 + (lane & 7) + ((lane >> 4) << 3);
                    const int col = kb + (lane & 8);
                    ldsm4(r, &Bsb[row * LDB0h + col]);
                } else {
                    const int row = kb + (lane & 15);
                    const int col = wn + jj * 16 + ((lane >> 4) << 3);
                    ldsm4t(r, &Bsb[row * LDB1h + col]);
                }
                bf[2 * jj + 0][0] = r[0];
                bf[2 * jj + 0][1] = r[1];
                bf[2 * jj + 1][0] = r[2];
                bf[2 * jj + 1][1] = r[3];
            }
#pragma unroll
            for (int i = 0; i < 4; i++)
#pragma unroll
                for (int j = 0; j < 4; j++)
                    mma16(acc[i][j], a[i], bf[j]);
        }
        __syncthreads();
    }

    // ---- epilogue ----
#pragma unroll
    for (int i = 0; i < 4; i++) {
        const int row0 = bMr + wm + i * 16 + (lane >> 2);
#pragma unroll
        for (int j = 0; j < 4; j++) {
            const int col0 = bNc + wn + j * 8 + ((lane & 3) << 1);
            float v0 = acc[i][j][0], v1 = acc[i][j][1];
            float v2 = acc[i][j][2], v3 = acc[i][j][3];
            if (EPI == 0) {
                float* Cb = (float*)Cv + (size_t)blockIdx.z * sC;
                *reinterpret_cast<float2*>(Cb + (size_t)row0 * N + col0) =
                    make_float2(v0, v1);
                *reinterpret_cast<float2*>(Cb + (size_t)(row0 + 8) * N + col0) =
                    make_float2(v2, v3);
            } else {
                if (EPI == 1) {
                    float b0 = bias[col0], b1 = bias[col0 + 1];
                    v0 += b0; v1 += b1; v2 += b0; v3 += b1;
                }
                if (EPI == 2) {
                    v0 = sigmoid_fast(0.0625f * v0);
                    v1 = sigmoid_fast(0.0625f * v1);
                    v2 = sigmoid_fast(0.0625f * v2);
                    v3 = sigmoid_fast(0.0625f * v3);
                }
                __half* Cb = (__half*)Cv + (size_t)blockIdx.z * sC;
                *reinterpret_cast<__half2*>(Cb + (size_t)row0 * N + col0) =
                    __floats2half2_rn(v0, v1);
                *reinterpret_cast<__half2*>(Cb + (size_t)(row0 + 8) * N + col0) =
                    __floats2half2_rn(v2, v3);
            }
        }
    }
}

extern "C" void kernel_launch(void* const* d_in, const int* in_sizes, int n_in,
                              void* d_out, int out_size)
{
    (void)in_sizes; (void)n_in; (void)out_size;
    const float* q  = (const float*)d_in[0];
    const float* k  = (const float*)d_in[1];
    const float* v  = (const float*)d_in[2];
    const float* Wq = (const float*)d_in[3];
    const float* bq = (const float*)d_in[4];
    const float* Wk = (const float*)d_in[5];
    const float* bk = (const float*)d_in[6];
    const float* Wv = (const float*)d_in[7];
    const float* bv = (const float*)d_in[8];
    float* out = (float*)d_out;

    __half *qh, *kh, *vh, *wq, *wk, *wv, *qp, *kp, *vp, *z;
    cudaGetSymbolAddress((void**)&qh, g_qh);
    cudaGetSymbolAddress((void**)&kh, g_kh);
    cudaGetSymbolAddress((void**)&vh, g_vh);
    cudaGetSymbolAddress((void**)&wq, g_wq);
    cudaGetSymbolAddress((void**)&wk, g_wk);
    cudaGetSymbolAddress((void**)&wv, g_wv);
    cudaGetSymbolAddress((void**)&qp, g_qp);
    cudaGetSymbolAddress((void**)&kp, g_kp);
    cudaGetSymbolAddress((void**)&vp, g_vp);
    cudaGetSymbolAddress((void**)&z,  g_z);

    const size_t SM0 = NSTG * (size_t)(BM * LDAh + BN * LDB0h) * 2;  // 61440 B
    const size_t SM1 = NSTG * (size_t)(BM * LDAh + BK * LDB1h) * 2;  // 56832 B
    cudaFuncSetAttribute(gemm_f16<0, 1>, cudaFuncAttributeMaxDynamicSharedMemorySize, (int)SM0);
    cudaFuncSetAttribute(gemm_f16<0, 2>, cudaFuncAttributeMaxDynamicSharedMemorySize, (int)SM0);
    cudaFuncSetAttribute(gemm_f16<1, 0>, cudaFuncAttributeMaxDynamicSharedMemorySize, (int)SM1);

    // prepass: fp32 -> fp16 (single launch; launch #1)
    const int n4_qkv = (4 * 4096 * 1024) / 4;
    to_half_all<<<dim3((n4_qkv + 255) / 256, 6), 256>>>(
        q, k, v, Wq, Wk, Wv, qh, kh, vh, wq, wk, wv);

    // Projections: M = 16384, K = 1024, W is [N,K].      (launches #2-#4)
    gemm_f16<0, 1><<<dim3(128, 2, 1), 256, SM0>>>(qh, wq, bq, qp,  256, 1024, 0, 0, 0);
    gemm_f16<0, 1><<<dim3(128, 2, 1), 256, SM0>>>(kh, wk, bk, kp,  256, 1024, 0, 0, 0);
    gemm_f16<0, 1><<<dim3(128, 8, 1), 256, SM0>>>(vh, wv, bv, vp, 1024, 1024, 0, 0, 0);

    // Scores + sigmoid: per batch M = N = 4096, K = 256.  (launch #5)
    gemm_f16<0, 2><<<dim3(32, 32, 4), 256, SM0>>>(
        qp, kp, nullptr, z, 4096, 256,
        (size_t)4096 * 256, (size_t)4096 * 256, (size_t)4096 * 4096);

    // Output: per batch M = 4096, N = 1024, K = 4096.     (launch #6 -> ncu -s 5)
    gemm_f16<1, 0><<<dim3(32, 8, 4), 256, SM1>>>(
        z, vp, nullptr, out, 1024, 4096,
        (size_t)4096 * 4096, (size_t)4096 * 1024, (size_t)4096 * 1024);
}

// round 15
// speedup vs baseline: 1.4019x; 1.1435x over previous
#include <cuda_runtime.h>
#include <cuda_fp16.h>

// ----------------------------------------------------------------------------
// ScaledDotProduct on GB300, round 13:
//   fp16 pipeline (fp32 accum), mma.sync m16n8k16 (tcgen05 unreachable:
//   harness builds via compute_103 PTX, 'a'-features rejected by ptxas),
//   CTA tile 128x128, 8 warps x (64x32), 2 CTA/SM,
//   BK=64 chunks + single __syncthreads per chunk (ring-safety by
//   NSTG=3 / depth-1 prefetch argument), ldmatrix.x4 fragment loads.
// ----------------------------------------------------------------------------

#define BM 128
#define BN 128
#define BK 64
#define LDAh  72   // halves: 64 + 8 pad (144B rows; ldmatrix conflict-free)
#define LDB0h 72   // B mode0 stored [n][k]
#define LDB1h 136  // B mode1 stored [k][n] (272B rows; ldmatrix conflict-free)
#define NSTG 3

// scratch (__device__ globals)
__device__ __align__(256) __half g_qh[(size_t)4 * 4096 * 1024];
__device__ __align__(256) __half g_kh[(size_t)4 * 4096 * 1024];
__device__ __align__(256) __half g_vh[(size_t)4 * 4096 * 1024];
__device__ __align__(256) __half g_wq[(size_t)256 * 1024];
__device__ __align__(256) __half g_wk[(size_t)256 * 1024];
__device__ __align__(256) __half g_wv[(size_t)1024 * 1024];
__device__ __align__(256) __half g_qp[(size_t)4 * 4096 * 256];
__device__ __align__(256) __half g_kp[(size_t)4 * 4096 * 256];
__device__ __align__(256) __half g_vp[(size_t)4 * 4096 * 1024];
__device__ __align__(256) __half g_z [(size_t)4 * 4096 * 4096];

__device__ __forceinline__ void cpasync16(void* dst, const void* src) {
    unsigned int d = (unsigned int)__cvta_generic_to_shared(dst);
    asm volatile("cp.async.cg.shared.global [%0], [%1], 16;" :: "r"(d), "l"(src));
}

__device__ __forceinline__ void ldsm4(unsigned int* r, const void* p) {
    unsigned int a = (unsigned int)__cvta_generic_to_shared(p);
    asm volatile("ldmatrix.sync.aligned.m8n8.x4.shared.b16 {%0,%1,%2,%3}, [%4];"
                 : "=r"(r[0]), "=r"(r[1]), "=r"(r[2]), "=r"(r[3]) : "r"(a));
}
__device__ __forceinline__ void ldsm4t(unsigned int* r, const void* p) {
    unsigned int a = (unsigned int)__cvta_generic_to_shared(p);
    asm volatile("ldmatrix.sync.aligned.m8n8.x4.trans.shared.b16 {%0,%1,%2,%3}, [%4];"
                 : "=r"(r[0]), "=r"(r[1]), "=r"(r[2]), "=r"(r[3]) : "r"(a));
}

__device__ __forceinline__ void mma16(float* c, const unsigned int* a, const unsigned int* b) {
    asm volatile(
        "mma.sync.aligned.m16n8k16.row.col.f32.f16.f16.f32 "
        "{%0,%1,%2,%3}, {%4,%5,%6,%7}, {%8,%9}, {%0,%1,%2,%3};\n"
        : "+f"(c[0]), "+f"(c[1]), "+f"(c[2]), "+f"(c[3])
        : "r"(a[0]), "r"(a[1]), "r"(a[2]), "r"(a[3]),
          "r"(b[0]), "r"(b[1]));
}

// sigma(x) = 1/(1 + 2^(-x*log2 e)) without any MUFU op.
__device__ __forceinline__ float sigmoid_fast(float x) {
    float t = x * -1.4426950408889634f;
    t = fminf(fmaxf(t, -30.0f), 30.0f);
    float fi = rintf(t);
    float f  = t - fi;
    float p = 1.33335581e-3f;
    p = fmaf(p, f, 9.61812911e-3f);
    p = fmaf(p, f, 5.55041087e-2f);
    p = fmaf(p, f, 2.40226507e-1f);
    p = fmaf(p, f, 6.93147181e-1f);
    p = fmaf(p, f, 1.0f);
    int ei = (int)fi;
    float s = __int_as_float((ei + 127) << 23);
    float d = fmaf(p, s, 1.0f);
    float r = __int_as_float(0x7EF311C3 - __float_as_int(d));
    r = r * fmaf(-d, r, 2.0f);
    r = r * fmaf(-d, r, 2.0f);
    r = r * fmaf(-d, r, 2.0f);
    return r;
}

// One launch converts all six tensors (segment selected by blockIdx.y).
__global__ void to_half_all(const float* __restrict__ q,  const float* __restrict__ k,
                            const float* __restrict__ v,  const float* __restrict__ Wq,
                            const float* __restrict__ Wk, const float* __restrict__ Wv,
                            __half* __restrict__ qh, __half* __restrict__ kh,
                            __half* __restrict__ vh, __half* __restrict__ wq,
                            __half* __restrict__ wk, __half* __restrict__ wv)
{
    const int seg = blockIdx.y;
    const float* in; __half* out; int n4;
    const int n4_qkv = (4 * 4096 * 1024) / 4;
    const int n4_wqk = (256 * 1024) / 4;
    const int n4_wv  = (1024 * 1024) / 4;
    switch (seg) {
        case 0: in = q;  out = qh; n4 = n4_qkv; break;
        case 1: in = k;  out = kh; n4 = n4_qkv; break;
        case 2: in = v;  out = vh; n4 = n4_qkv; break;
        case 3: in = Wq; out = wq; n4 = n4_wqk; break;
        case 4: in = Wk; out = wk; n4 = n4_wqk; break;
        default:in = Wv; out = wv; n4 = n4_wv;  break;
    }
    int i = blockIdx.x * blockDim.x + threadIdx.x;
    if (i < n4) {
        float4 val = reinterpret_cast<const float4*>(in)[i];
        __half2 h0 = __floats2half2_rn(val.x, val.y);
        __half2 h1 = __floats2half2_rn(val.z, val.w);
        reinterpret_cast<uint2*>(out)[i] =
            make_uint2(*reinterpret_cast<unsigned int*>(&h0),
                       *reinterpret_cast<unsigned int*>(&h1));
    }
}

// MODE_B: 0 -> B is [N,K] half (A @ B^T); 1 -> B is [K,N] half (A @ B)
// EPI:    0 -> fp32 store, 1 -> +bias half store, 2 -> sigmoid(x/16) half store
template <int MODE_B, int EPI>
__global__ __launch_bounds__(256, 2)
void gemm_f16(const __half* __restrict__ A, const __half* __restrict__ B,
              const float* __restrict__ bias, void* __restrict__ Cv,
              int N, int K,
              size_t sA, size_t sB, size_t sC)
{
    extern __shared__ __half sm[];
    constexpr int ASZ = BM * LDAh;                                 // 9216 halves
    constexpr int BSZ = (MODE_B == 0) ? BN * LDB0h : BK * LDB1h;   // 9216 / 8704
    constexpr int STW = ASZ + BSZ;

    const __half* Ab = A + (size_t)blockIdx.z * sA;
    const __half* Bb = B + (size_t)blockIdx.z * sB;

    const int bMr  = blockIdx.x * BM;
    const int bNc  = blockIdx.y * BN;
    const int tid  = threadIdx.x;
    const int lane = tid & 31;
    const int warp = tid >> 5;
    const int wm   = (warp >> 2) * 64;   // 2 warps along M
    const int wn   = (warp & 3) * 32;    // 4 warps along N

    float acc[4][4][4];
#pragma unroll
    for (int i = 0; i < 4; i++)
#pragma unroll
        for (int j = 0; j < 4; j++)
#pragma unroll
            for (int t = 0; t < 4; t++) acc[i][j][t] = 0.0f;

    const int nch = K / BK;

    auto stage = [&](int s, int k0) {
        __half* Ad = sm + s * STW;
        __half* Bd = Ad + ASZ;
        // A tile: 128 rows x 64 halves = 8 x 16B chunks/row, 1024 chunks
#pragma unroll
        for (int it = 0; it < 4; it++) {
            int f4 = tid + it * 256;
            int r  = f4 >> 3;
            int cc = (f4 & 7) << 3;
            cpasync16(&Ad[r * LDAh + cc], Ab + (size_t)(bMr + r) * K + k0 + cc);
        }
        if (MODE_B == 0) {
            // B[n][k]: 128 rows x 64 halves, 1024 chunks
#pragma unroll
            for (int it = 0; it < 4; it++) {
                int f4 = tid + it * 256;
                int r  = f4 >> 3;
                int cc = (f4 & 7) << 3;
                cpasync16(&Bd[r * LDB0h + cc], Bb + (size_t)(bNc + r) * K + k0 + cc);
            }
        } else {
            // B[k][n]: 64 rows x 128 halves, 1024 chunks
#pragma unroll
            for (int it = 0; it < 4; it++) {
                int f4 = tid + it * 256;
                int r  = f4 >> 4;
                int cc = (f4 & 15) << 3;
                cpasync16(&Bd[r * LDB1h + cc], Bb + (size_t)(k0 + r) * N + bNc + cc);
            }
        }
        asm volatile("cp.async.commit_group;");
    };

    stage(0, 0);

    for (int c = 0; c < nch; c++) {
        // Stage c+1 BEFORE this iteration's sync. Ring safety (NSTG=3):
        // buffer (c+1)%3 was last read in compute of iteration c-2; every warp
        // here has passed sync(c-1), which globally orders those reads before
        // these writes. One sync per chunk total.
        if (c + 1 < nch) {
            stage((c + 1) % NSTG, (c + 1) * BK);
            asm volatile("cp.async.wait_group 1;");
        } else {
            asm volatile("cp.async.wait_group 0;");
        }
        __syncthreads();

        const __half* Asb = sm + (c % NSTG) * STW;
        const __half* Bsb = Asb + ASZ;

#pragma unroll
        for (int ks = 0; ks < 4; ks++) {            // four k16 steps per BK=64
            const int kb = ks * 16;                 // halves
            unsigned int a[4][4], bf[4][2];
#pragma unroll
            for (int i = 0; i < 4; i++) {
                const int row = wm + i * 16 + (lane & 15);
                const int col = kb + ((lane >> 4) << 3);
                ldsm4(a[i], &Asb[row * LDAh + col]);
            }
#pragma unroll
            for (int jj = 0; jj < 2; jj++) {
                unsigned int r[4];
                if (MODE_B == 0) {
                    const int row = wn + jj * 16 + (lane & 7) + ((lane >> 4) << 3);
                    const int col = kb + (lane & 8);
                    ldsm4(r, &Bsb[row * LDB0h + col]);
                } else {
                    const int row = kb + (lane & 15);
                    const int col = wn + jj * 16 + ((lane >> 4) << 3);
                    ldsm4t(r, &Bsb[row * LDB1h + col]);
                }
                bf[2 * jj + 0][0] = r[0];
                bf[2 * jj + 0][1] = r[1];
                bf[2 * jj + 1][0] = r[2];
                bf[2 * jj + 1][1] = r[3];
            }
#pragma unroll
            for (int i = 0; i < 4; i++)
#pragma unroll
                for (int j = 0; j < 4; j++)
                    mma16(acc[i][j], a[i], bf[j]);
        }
    }

    // ---- epilogue ----
#pragma unroll
    for (int i = 0; i < 4; i++) {
        const int row0 = bMr + wm + i * 16 + (lane >> 2);
#pragma unroll
        for (int j = 0; j < 4; j++) {
            const int col0 = bNc + wn + j * 8 + ((lane & 3) << 1);
            float v0 = acc[i][j][0], v1 = acc[i][j][1];
            float v2 = acc[i][j][2], v3 = acc[i][j][3];
            if (EPI == 0) {
                float* Cb = (float*)Cv + (size_t)blockIdx.z * sC;
                *reinterpret_cast<float2*>(Cb + (size_t)row0 * N + col0) =
                    make_float2(v0, v1);
                *reinterpret_cast<float2*>(Cb + (size_t)(row0 + 8) * N + col0) =
                    make_float2(v2, v3);
            } else {
                if (EPI == 1) {
                    float b0 = bias[col0], b1 = bias[col0 + 1];
                    v0 += b0; v1 += b1; v2 += b0; v3 += b1;
                }
                if (EPI == 2) {
                    v0 = sigmoid_fast(0.0625f * v0);
                    v1 = sigmoid_fast(0.0625f * v1);
                    v2 = sigmoid_fast(0.0625f * v2);
                    v3 = sigmoid_fast(0.0625f * v3);
                }
                __half* Cb = (__half*)Cv + (size_t)blockIdx.z * sC;
                *reinterpret_cast<__half2*>(Cb + (size_t)row0 * N + col0) =
                    __floats2half2_rn(v0, v1);
                *reinterpret_cast<__half2*>(Cb + (size_t)(row0 + 8) * N + col0) =
                    __floats2half2_rn(v2, v3);
            }
        }
    }
}

extern "C" void kernel_launch(void* const* d_in, const int* in_sizes, int n_in,
                              void* d_out, int out_size)
{
    (void)in_sizes; (void)n_in; (void)out_size;
    const float* q  = (const float*)d_in[0];
    const float* k  = (const float*)d_in[1];
    const float* v  = (const float*)d_in[2];
    const float* Wq = (const float*)d_in[3];
    const float* bq = (const float*)d_in[4];
    const float* Wk = (const float*)d_in[5];
    const float* bk = (const float*)d_in[6];
    const float* Wv = (const float*)d_in[7];
    const float* bv = (const float*)d_in[8];
    float* out = (float*)d_out;

    __half *qh, *kh, *vh, *wq, *wk, *wv, *qp, *kp, *vp, *z;
    cudaGetSymbolAddress((void**)&qh, g_qh);
    cudaGetSymbolAddress((void**)&kh, g_kh);
    cudaGetSymbolAddress((void**)&vh, g_vh);
    cudaGetSymbolAddress((void**)&wq, g_wq);
    cudaGetSymbolAddress((void**)&wk, g_wk);
    cudaGetSymbolAddress((void**)&wv, g_wv);
    cudaGetSymbolAddress((void**)&qp, g_qp);
    cudaGetSymbolAddress((void**)&kp, g_kp);
    cudaGetSymbolAddress((void**)&vp, g_vp);
    cudaGetSymbolAddress((void**)&z,  g_z);

    const size_t SM0 = NSTG * (size_t)(BM * LDAh + BN * LDB0h) * 2;  // 110592 B
    const size_t SM1 = NSTG * (size_t)(BM * LDAh + BK * LDB1h) * 2;  // 107520 B
    cudaFuncSetAttribute(gemm_f16<0, 1>, cudaFuncAttributeMaxDynamicSharedMemorySize, (int)SM0);
    cudaFuncSetAttribute(gemm_f16<0, 2>, cudaFuncAttributeMaxDynamicSharedMemorySize, (int)SM0);
    cudaFuncSetAttribute(gemm_f16<1, 0>, cudaFuncAttributeMaxDynamicSharedMemorySize, (int)SM1);

    // 1) prepass fp32 -> fp16 (single launch)
    const int n4_qkv = (4 * 4096 * 1024) / 4;
    to_half_all<<<dim3((n4_qkv + 255) / 256, 6), 256>>>(
        q, k, v, Wq, Wk, Wv, qh, kh, vh, wq, wk, wv);

    // 2-4) Projections: M = 16384, K = 1024, W is [N,K].
    gemm_f16<0, 1><<<dim3(128, 2, 1), 256, SM0>>>(qh, wq, bq, qp,  256, 1024, 0, 0, 0);
    gemm_f16<0, 1><<<dim3(128, 2, 1), 256, SM0>>>(kh, wk, bk, kp,  256, 1024, 0, 0, 0);
    gemm_f16<0, 1><<<dim3(128, 8, 1), 256, SM0>>>(vh, wv, bv, vp, 1024, 1024, 0, 0, 0);

    // 5) Scores + sigmoid: per batch M = N = 4096, K = 256.
    gemm_f16<0, 2><<<dim3(32, 32, 4), 256, SM0>>>(
        qp, kp, nullptr, z, 4096, 256,
        (size_t)4096 * 256, (size_t)4096 * 256, (size_t)4096 * 4096);

    // 6) Output: per batch M = 4096, N = 1024, K = 4096.  (ncu -s 5 target)
    gemm_f16<1, 0><<<dim3(32, 8, 4), 256, SM1>>>(
        z, vp, nullptr, out, 1024, 4096,
        (size_t)4096 * 4096, (size_t)4096 * 1024, (size_t)4096 * 1024);
}